// round 12
// baseline (speedup 1.0000x reference)
#include <cuda_runtime.h>
#include <cuda_bf16.h>
#include <cstdint>

// Problem constants: N=4096, L_V=64, H=512, D=256
constexpr int NB   = 4096;
constexpr int LV   = 64;
constexpr int HD   = 512;
constexpr int DD   = 256;
constexpr int K1   = 3 * DD;   // 768
constexpr int KTOT = K1 + HD;  // 1280

// GEMM tiling: CTA tile 128x128, K stepped by 16 (one m16n8k16 per step)
constexpr int BM = 128, BN = 128, BKS = 16;
constexpr int NIT = KTOT / BKS;                    // 80
constexpr int GEMM_CTAS  = (NB / BM) * (HD / BN);  // 128
constexpr int TOTAL_CTAS = 304;                    // 2 per SM on 152 SMs

// Copy pool
constexpr int ROWS_TOTAL = NB * LV;                // 262144 rows of 512 floats
constexpr int NUM_GRABS  = ROWS_TOTAL / 32;        // 8192

// W-prep: transpose tiles (k x n)
constexpr int WKT = 64, WNT = 32;
constexpr int WBLOCKS = (KTOT / WKT) * (HD / WNT); // 20*16 = 320

// fused smem: 2 stages x 24KB
//   per stage: xf32[128][16] f32 @0 (8KB) | whi[128][16]bf16 @8K (4KB)
//              | wlo @12K (4KB) | xhi(conv) @16K (4KB) | xlo(conv) @20K (4KB)
constexpr uint32_t STAGE = 24576;

__device__ int g_copy_ctr;                         // zero-init; prep resets
__device__ __align__(16) __nv_bfloat16 g_whi[HD * KTOT];  // W^T hi (k-major)
__device__ __align__(16) __nv_bfloat16 g_wlo[HD * KTOT];  // W^T lo

// ---------------- PTX helpers ----------------
__device__ __forceinline__ uint32_t s2u(const void* p) {
    uint32_t a;
    asm("{ .reg .u64 t; cvta.to.shared.u64 t, %1; cvt.u32.u64 %0, t; }"
        : "=r"(a) : "l"(p));
    return a;
}
__device__ __forceinline__ void cp16(uint32_t dst, const void* src) {
    asm volatile("cp.async.cg.shared.global [%0], [%1], 16;" :: "r"(dst), "l"(src));
}
__device__ __forceinline__ void cp_commit() {
    asm volatile("cp.async.commit_group;");
}
template <int N>
__device__ __forceinline__ void cp_wait() {
    asm volatile("cp.async.wait_group %0;" :: "n"(N));
}
__device__ __forceinline__ void ldsm4(uint32_t* r, uint32_t addr) {
    asm volatile("ldmatrix.sync.aligned.m8n8.x4.shared.b16 {%0,%1,%2,%3}, [%4];"
                 : "=r"(r[0]), "=r"(r[1]), "=r"(r[2]), "=r"(r[3]) : "r"(addr));
}
__device__ __forceinline__ void mma16816(float* d, const uint32_t* a,
                                         const uint32_t* b) {
    asm volatile(
        "mma.sync.aligned.m16n8k16.row.col.f32.bf16.bf16.f32 "
        "{%0,%1,%2,%3}, {%4,%5,%6,%7}, {%8,%9}, {%0,%1,%2,%3};"
        : "+f"(d[0]), "+f"(d[1]), "+f"(d[2]), "+f"(d[3])
        : "r"(a[0]), "r"(a[1]), "r"(a[2]), "r"(a[3]), "r"(b[0]), "r"(b[1]));
}
__device__ __forceinline__ float4 ldcs(const float4* p) {
    float4 v;
    asm volatile("ld.global.cs.v4.f32 {%0,%1,%2,%3}, [%4];"
                 : "=f"(v.x), "=f"(v.y), "=f"(v.z), "=f"(v.w) : "l"(p));
    return v;
}
__device__ __forceinline__ void stcs(float4* p, float4 v) {
    asm volatile("st.global.cs.v4.f32 [%0], {%1,%2,%3,%4};"
                 :: "l"(p), "f"(v.x), "f"(v.y), "f"(v.z), "f"(v.w) : "memory");
}
__device__ __forceinline__ void sts128(uint32_t addr, uint32_t a, uint32_t b,
                                       uint32_t c, uint32_t d) {
    asm volatile("st.shared.v4.b32 [%0], {%1,%2,%3,%4};"
                 :: "r"(addr), "r"(a), "r"(b), "r"(c), "r"(d) : "memory");
}
__device__ __forceinline__ uint32_t pack_hi2(float a, float b,
                                             float& ra, float& rb) {
    __nv_bfloat16 h0 = __float2bfloat16_rn(a);
    __nv_bfloat16 h1 = __float2bfloat16_rn(b);
    ra = a - __bfloat162float(h0);
    rb = b - __bfloat162float(h1);
    return ((uint32_t)*(uint16_t*)&h1 << 16) | *(uint16_t*)&h0;
}
__device__ __forceinline__ uint32_t pack_bf2(float a, float b) {
    __nv_bfloat162 t = __floats2bfloat162_rn(a, b);
    return *reinterpret_cast<uint32_t*>(&t);
}

// --------------------------------------------------------------------------
// prep kernel (W only): W^T (k-major) -> bf16 hi/lo via smem tile transpose.
// Block 0 thread 0 also resets the copy counter.
// --------------------------------------------------------------------------
__global__ __launch_bounds__(256)
void prep_kernel(const float* __restrict__ W_in,
                 const float* __restrict__ W_h)
{
    if (blockIdx.x == 0 && threadIdx.x == 0) g_copy_ctr = 0;
    const int tid = threadIdx.x;

    __shared__ float tile[WKT][WNT + 1];
    const int k0   = ((int)blockIdx.x % (KTOT / WKT)) * WKT;  // mult of 64;
    const int n0   = ((int)blockIdx.x / (KTOT / WKT)) * WNT;  // never straddles K1
    const float* W = (k0 < K1) ? (W_in + (size_t)k0 * HD)
                               : (W_h + (size_t)(k0 - K1) * HD);
    #pragma unroll
    for (int i = 0; i < 8; i++) {
        const int e = tid + i * 256;
        const int r = e >> 5;
        const int c = e & 31;
        tile[r][c] = W[(size_t)r * HD + n0 + c];
    }
    __syncthreads();
    #pragma unroll
    for (int i = 0; i < 4; i++) {
        const int p  = tid + i * 256;
        const int n  = p >> 5;
        const int kk = (p & 31) * 2;
        float r0, r1;
        const uint32_t hi = pack_hi2(tile[kk][n], tile[kk + 1][n], r0, r1);
        const uint32_t lo = pack_bf2(r0, r1);
        const size_t off = (size_t)(n0 + n) * KTOT + k0 + kk;
        *(uint32_t*)&g_whi[off] = hi;
        *(uint32_t*)&g_wlo[off] = lo;
    }
}

// --------------------------------------------------------------------------
// Copy role: work-stealing passthrough, skipping the row each batch's GEMM
// scatters. Warp grabs 32 rows; 4 rows/group with 16 LDG.128 in flight.
// --------------------------------------------------------------------------
__device__ __forceinline__ void copy_role(const float4* __restrict__ src,
                                          float4* __restrict__ dst,
                                          const int* __restrict__ veh_idx,
                                          int lane)
{
    for (;;) {
        int c;
        if (lane == 0) c = atomicAdd(&g_copy_ctr, 1);
        c = __shfl_sync(0xffffffffu, c, 0);
        if (c >= NUM_GRABS) return;

        const int r0   = c * 32;            // same n for the whole grab
        const int n    = r0 >> 6;
        const int skip = veh_idx[n] & (LV - 1);
        const int l0   = r0 & 63;

        for (int g = 0; g < 8; g++) {
            float4 v[16];
            size_t base = (size_t)(r0 + g * 4) * (HD / 4) + lane;
            #pragma unroll
            for (int rr = 0; rr < 4; rr++)
                #pragma unroll
                for (int q = 0; q < 4; q++)
                    v[rr * 4 + q] = ldcs(src + base + rr * 128 + q * 32);
            #pragma unroll
            for (int rr = 0; rr < 4; rr++) {
                if (l0 + g * 4 + rr == skip) continue;   // GEMM writes this row
                #pragma unroll
                for (int q = 0; q < 4; q++)
                    stcs(dst + base + rr * 128 + q * 32, v[rr * 4 + q]);
            }
        }
    }
}

// --------------------------------------------------------------------------
// Fused kernel. bids [0,128): tensor-core GEMM tile (mma.sync bf16, 3-term
// hi/lo split). X is read as raw fp32 and split in-kernel; W planes come
// pre-split from prep. 2-stage cp.async pipeline (48KB). Epilogue scatters
// tanh(acc+bias) directly into out[n, veh_idx[n], :]. All CTAs end in the
// copy pool.
// --------------------------------------------------------------------------
__global__ __launch_bounds__(256, 2)
void fused_kernel(const float* __restrict__ memory,
                  const int*   __restrict__ veh_idx,
                  const float* __restrict__ veh_repr,
                  const float* __restrict__ cust_repr,
                  const float* __restrict__ edge_emb,
                  const float* __restrict__ b_in,
                  const float* __restrict__ b_h,
                  float* __restrict__ out)
{
    __shared__ __align__(128) char raw[2 * STAGE];   // 48KB

    const int tid  = threadIdx.x;
    const int bid  = blockIdx.x;
    const int lane = tid & 31;

    if (bid < GEMM_CTAS) {
        const int block_m = (bid >> 2) * BM;
        const int block_n = (bid & 3) * BN;
        const int w  = tid >> 5;
        const int wm = w >> 1;          // 0..3 -> rows wm*32
        const int wn = w & 1;           // 0..1 -> cols wn*64
        const uint32_t sbase = s2u(raw);

        // ---- X fp32 cp.async mapping: 512 16B-chunks; 2/thread ----
        const int xr0 = tid >> 2;            // row 0..63
        const int xr1 = xr0 + 64;            // row 64..127
        const int xq  = (tid & 3) * 4;       // float offset 0,4,8,12
        const int gm0 = block_m + xr0;
        const int gm1 = block_m + xr1;
        const size_t memrow0 = ((size_t)gm0 * LV + (veh_idx[gm0] & (LV - 1))) * HD;
        const size_t memrow1 = ((size_t)gm1 * LV + (veh_idx[gm1] & (LV - 1))) * HD;
        const uint32_t xDst0 = sbase + (uint32_t)(xr0 * 64 + xq * 4);
        const uint32_t xDst1 = sbase + (uint32_t)(xr1 * 64 + xq * 4);

        // ---- W cp.async mapping: 256 chunks per plane; 1/thread each ----
        const int wr = tid >> 1;             // row 0..127
        const int wh = tid & 1;              // 16B half
        const uint32_t wDhi = sbase + 8192  + (uint32_t)(wr * 32 + wh * 16);
        const uint32_t wDlo = sbase + 12288 + (uint32_t)(wr * 32 + wh * 16);
        const size_t gwoff = (size_t)(block_n + wr) * KTOT + wh * 8;

        auto issue = [&](int it, int buf) {
            const int k0 = it * BKS;
            const uint32_t so = (uint32_t)buf * STAGE;
            const float *s0, *s1;
            if (k0 < DD) {
                s0 = veh_repr + (size_t)gm0 * DD + k0 + xq;
                s1 = veh_repr + (size_t)gm1 * DD + k0 + xq;
            } else if (k0 < 2 * DD) {
                const int o = k0 - DD;
                s0 = cust_repr + (size_t)gm0 * DD + o + xq;
                s1 = cust_repr + (size_t)gm1 * DD + o + xq;
            } else if (k0 < K1) {
                const int o = k0 - 2 * DD;
                s0 = edge_emb + (size_t)gm0 * DD + o + xq;
                s1 = edge_emb + (size_t)gm1 * DD + o + xq;
            } else {
                const int o = k0 - K1;
                s0 = memory + memrow0 + o + xq;
                s1 = memory + memrow1 + o + xq;
            }
            cp16(xDst0 + so, s0);
            cp16(xDst1 + so, s1);
            cp16(wDhi + so, g_whi + gwoff + k0);
            cp16(wDlo + so, g_wlo + gwoff + k0);
            cp_commit();
        };

        // ---- convert mapping: thread -> (row, 8-float half) ----
        const int crow  = tid >> 1;
        const int chalf = tid & 1;
        const uint32_t cSrc = sbase + (uint32_t)(crow * 64 + chalf * 32);
        const uint32_t cHi  = sbase + 16384 + (uint32_t)(crow * 32 + chalf * 16);
        const uint32_t cLo  = sbase + 20480 + (uint32_t)(crow * 32 + chalf * 16);

        // ---- ldmatrix lane offsets (within stage) ----
        uint32_t aoff[2];
        #pragma unroll
        for (int i = 0; i < 2; i++) {
            const int r = wm * 32 + i * 16 + (lane & 7) + ((lane >> 3) & 1) * 8;
            aoff[i] = (uint32_t)(r * 32 + ((lane >> 4) & 1) * 16);
        }
        uint32_t boff[4];
        #pragma unroll
        for (int p = 0; p < 4; p++) {
            const int r = wn * 64 + p * 16 + (lane & 7) + ((lane >> 4) & 1) * 8;
            boff[p] = (uint32_t)(r * 32 + ((lane >> 3) & 1) * 16);
        }

        float d[2][8][4];
        #pragma unroll
        for (int i = 0; i < 2; i++)
            #pragma unroll
            for (int j = 0; j < 8; j++)
                #pragma unroll
                for (int q = 0; q < 4; q++) d[i][j][q] = 0.0f;

        issue(0, 0);
        issue(1, 1);

        for (int it = 0; it < NIT; it++) {
            const int buf = it & 1;
            const uint32_t sb = sbase + (uint32_t)buf * STAGE;

            if (it + 2 < NIT) cp_wait<1>(); else cp_wait<0>();
            __syncthreads();                 // stage 'it' data landed

            // ---- in-kernel X hi/lo split: 8 floats/thread ----
            {
                float xf[8];
                *(float4*)&xf[0] = *(const float4*)(raw + (cSrc - sbase));
                *(float4*)&xf[4] = *(const float4*)(raw + (cSrc - sbase) + 16);
                // note: cSrc already includes buf? No — add stage offset:
                const char* src = raw + buf * STAGE + (crow * 64 + chalf * 32);
                *(float4*)&xf[0] = *(const float4*)(src);
                *(float4*)&xf[4] = *(const float4*)(src + 16);
                float r0, r1;
                uint32_t h[4], l[4];
                #pragma unroll
                for (int e = 0; e < 4; e++) {
                    h[e] = pack_hi2(xf[2 * e], xf[2 * e + 1], r0, r1);
                    l[e] = pack_bf2(r0, r1);
                }
                sts128(cHi + (uint32_t)buf * STAGE, h[0], h[1], h[2], h[3]);
                sts128(cLo + (uint32_t)buf * STAGE, l[0], l[1], l[2], l[3]);
            }
            __syncthreads();                 // conversions visible CTA-wide

            uint32_t ah[2][4], al[2][4], bb[8][2];
            ldsm4(ah[0], sb + 16384 + aoff[0]);
            ldsm4(ah[1], sb + 16384 + aoff[1]);
            ldsm4(al[0], sb + 20480 + aoff[0]);
            ldsm4(al[1], sb + 20480 + aoff[1]);
            #pragma unroll
            for (int p = 0; p < 4; p++) {
                uint32_t r[4];
                ldsm4(r, sb + 8192 + boff[p]);      // W hi
                bb[2 * p][0] = r[0]; bb[2 * p][1] = r[1];
                bb[2 * p + 1][0] = r[2]; bb[2 * p + 1][1] = r[3];
            }
            #pragma unroll
            for (int i = 0; i < 2; i++)
                #pragma unroll
                for (int j = 0; j < 8; j++) {
                    mma16816(d[i][j], ah[i], bb[j]);   // hi*hi
                    mma16816(d[i][j], al[i], bb[j]);   // lo*hi
                }
            #pragma unroll
            for (int p = 0; p < 4; p++) {
                uint32_t r[4];
                ldsm4(r, sb + 12288 + boff[p]);     // W lo
                bb[2 * p][0] = r[0]; bb[2 * p][1] = r[1];
                bb[2 * p + 1][0] = r[2]; bb[2 * p + 1][1] = r[3];
            }
            #pragma unroll
            for (int i = 0; i < 2; i++)
                #pragma unroll
                for (int j = 0; j < 8; j++)
                    mma16816(d[i][j], ah[i], bb[j]);   // hi*lo

            __syncthreads();                 // all warps done with stage buf
            if (it + 2 < NIT) issue(it + 2, buf);
        }

        // epilogue: bias + tanh -> scatter directly to out[n, idx[n], :]
        float2 bias[8];
        #pragma unroll
        for (int j = 0; j < 8; j++) {
            const int col = block_n + wn * 64 + j * 8 + (lane & 3) * 2;
            bias[j].x = b_in[col] + b_h[col];
            bias[j].y = b_in[col + 1] + b_h[col + 1];
        }
        #pragma unroll
        for (int i = 0; i < 2; i++) {
            const int m0 = block_m + wm * 32 + i * 16 + (lane >> 2);
            const int m1 = m0 + 8;
            const size_t base0 = ((size_t)m0 * LV + (veh_idx[m0] & (LV - 1))) * HD;
            const size_t base1 = ((size_t)m1 * LV + (veh_idx[m1] & (LV - 1))) * HD;
            #pragma unroll
            for (int j = 0; j < 8; j++) {
                const int col = block_n + wn * 64 + j * 8 + (lane & 3) * 2;
                float2 v0, v1;
                v0.x = tanhf(d[i][j][0] + bias[j].x);
                v0.y = tanhf(d[i][j][1] + bias[j].y);
                v1.x = tanhf(d[i][j][2] + bias[j].x);
                v1.y = tanhf(d[i][j][3] + bias[j].y);
                *(float2*)&out[base0 + col] = v0;
                *(float2*)&out[base1 + col] = v1;
            }
        }
    }

    // Copy pool (copy-only CTAs arrive here immediately; no smem used).
    copy_role((const float4*)memory, (float4*)out, veh_idx, lane);
}

extern "C" void kernel_launch(void* const* d_in, const int* in_sizes, int n_in,
                              void* d_out, int out_size)
{
    const float* memory    = (const float*)d_in[0];
    const int*   veh_idx   = (const int*)d_in[1];
    const float* veh_repr  = (const float*)d_in[2];
    const float* cust_repr = (const float*)d_in[3];
    const float* edge_emb  = (const float*)d_in[4];
    const float* W_in      = (const float*)d_in[5];
    const float* b_in      = (const float*)d_in[6];
    const float* W_h       = (const float*)d_in[7];
    const float* b_h       = (const float*)d_in[8];
    float*       out       = (float*)d_out;

    prep_kernel<<<WBLOCKS, 256>>>(W_in, W_h);
    fused_kernel<<<TOTAL_CTAS, 256>>>(memory, veh_idx, veh_repr, cust_repr,
                                      edge_emb, b_in, b_h, out);
}

// round 13
// speedup vs baseline: 1.1447x; 1.1447x over previous
#include <cuda_runtime.h>
#include <cuda_bf16.h>
#include <cstdint>

// Problem constants: N=4096, L_V=64, H=512, D=256
constexpr int NB   = 4096;
constexpr int LV   = 64;
constexpr int HD   = 512;
constexpr int DD   = 256;
constexpr int K1   = 3 * DD;   // 768
constexpr int KTOT = K1 + HD;  // 1280

// GEMM tiling: CTA tile 128x128, K stepped by 16 (one m16n8k16 per step)
constexpr int BM = 128, BN = 128, BKS = 16;
constexpr int NIT = KTOT / BKS;                    // 80
constexpr int GEMM_CTAS  = (NB / BM) * (HD / BN);  // 128
constexpr int TOTAL_CTAS = 304;                    // 2 per SM on 152 SMs

// Copy pool
constexpr int ROWS_TOTAL = NB * LV;                // 262144 rows of 512 floats
constexpr int NUM_GRABS  = ROWS_TOTAL / 32;        // 8192

// prep: X conversion (4 chunks/thread, batched) + W transpose tiles
constexpr int XCHUNKS  = NB * KTOT / 4;            // 1,310,720 float4 chunks
constexpr int XBLOCKS  = XCHUNKS / (256 * 4);      // 1280
constexpr int XSTRIDE  = XBLOCKS * 256;            // 327,680
constexpr int WKT = 64, WNT = 32;
constexpr int WBLOCKS = (KTOT / WKT) * (HD / WNT); // 320

__device__ int g_copy_ctr;                         // zero-init; prep resets
__device__ __align__(16) __nv_bfloat16 g_xhi[NB * KTOT];  // X hi plane (10MB)
__device__ __align__(16) __nv_bfloat16 g_xlo[NB * KTOT];  // X lo plane
__device__ __align__(16) __nv_bfloat16 g_whi[HD * KTOT];  // W^T hi (k-major)
__device__ __align__(16) __nv_bfloat16 g_wlo[HD * KTOT];  // W^T lo

// ---------------- PTX helpers ----------------
__device__ __forceinline__ uint32_t s2u(const void* p) {
    uint32_t a;
    asm("{ .reg .u64 t; cvta.to.shared.u64 t, %1; cvt.u32.u64 %0, t; }"
        : "=r"(a) : "l"(p));
    return a;
}
__device__ __forceinline__ void cp16(uint32_t dst, const void* src) {
    asm volatile("cp.async.cg.shared.global [%0], [%1], 16;" :: "r"(dst), "l"(src));
}
__device__ __forceinline__ void cp_commit() {
    asm volatile("cp.async.commit_group;");
}
template <int N>
__device__ __forceinline__ void cp_wait() {
    asm volatile("cp.async.wait_group %0;" :: "n"(N));
}
__device__ __forceinline__ void ldsm4(uint32_t* r, uint32_t addr) {
    asm volatile("ldmatrix.sync.aligned.m8n8.x4.shared.b16 {%0,%1,%2,%3}, [%4];"
                 : "=r"(r[0]), "=r"(r[1]), "=r"(r[2]), "=r"(r[3]) : "r"(addr));
}
__device__ __forceinline__ void mma16816(float* d, const uint32_t* a,
                                         const uint32_t* b) {
    asm volatile(
        "mma.sync.aligned.m16n8k16.row.col.f32.bf16.bf16.f32 "
        "{%0,%1,%2,%3}, {%4,%5,%6,%7}, {%8,%9}, {%0,%1,%2,%3};"
        : "+f"(d[0]), "+f"(d[1]), "+f"(d[2]), "+f"(d[3])
        : "r"(a[0]), "r"(a[1]), "r"(a[2]), "r"(a[3]), "r"(b[0]), "r"(b[1]));
}
__device__ __forceinline__ float4 ldcs(const float4* p) {
    float4 v;
    asm volatile("ld.global.cs.v4.f32 {%0,%1,%2,%3}, [%4];"
                 : "=f"(v.x), "=f"(v.y), "=f"(v.z), "=f"(v.w) : "l"(p));
    return v;
}
__device__ __forceinline__ void stcs(float4* p, float4 v) {
    asm volatile("st.global.cs.v4.f32 [%0], {%1,%2,%3,%4};"
                 :: "l"(p), "f"(v.x), "f"(v.y), "f"(v.z), "f"(v.w) : "memory");
}
__device__ __forceinline__ uint32_t pack_hi2(float a, float b,
                                             float& ra, float& rb) {
    __nv_bfloat16 h0 = __float2bfloat16_rn(a);
    __nv_bfloat16 h1 = __float2bfloat16_rn(b);
    ra = a - __bfloat162float(h0);
    rb = b - __bfloat162float(h1);
    return ((uint32_t)*(uint16_t*)&h1 << 16) | *(uint16_t*)&h0;
}
__device__ __forceinline__ uint32_t pack_bf2(float a, float b) {
    __nv_bfloat162 t = __floats2bfloat162_rn(a, b);
    return *reinterpret_cast<uint32_t*>(&t);
}

// --------------------------------------------------------------------------
// prep kernel:
//  blocks [0, XBLOCKS):  X = concat(veh,cust,edge,cur_h) -> bf16 hi/lo planes.
//    4 independent float4 chunks per thread, loads batched first (MLP=4).
//  blocks [XBLOCKS, +WBLOCKS): W^T (k-major) -> hi/lo via smem transpose.
//  block 0 thread 0 resets the copy-pool counter.
// --------------------------------------------------------------------------
__global__ __launch_bounds__(256)
void prep_kernel(const float* __restrict__ memory,
                 const int*   __restrict__ veh_idx,
                 const float* __restrict__ veh_repr,
                 const float* __restrict__ cust_repr,
                 const float* __restrict__ edge_emb,
                 const float* __restrict__ W_in,
                 const float* __restrict__ W_h)
{
    if (blockIdx.x == 0 && threadIdx.x == 0) g_copy_ctr = 0;
    const int tid = threadIdx.x;

    if (blockIdx.x < XBLOCKS) {
        const int base = blockIdx.x * 256 + tid;
        float4 v[4];
        int    e[4];
        #pragma unroll
        for (int u = 0; u < 4; u++) {
            const int ch = base + u * XSTRIDE;
            e[u] = ch * 4;                   // float index; 16B chunk never
            const int m = e[u] / KTOT;       // crosses a 256-float region edge
            const int k = e[u] % KTOT;
            const float* src;
            if (k < DD)            src = veh_repr  + (size_t)m * DD + k;
            else if (k < 2 * DD)   src = cust_repr + (size_t)m * DD + (k - DD);
            else if (k < K1)       src = edge_emb  + (size_t)m * DD + (k - 2 * DD);
            else {
                const int idx = veh_idx[m] & (LV - 1);
                src = memory + ((size_t)m * LV + idx) * HD + (k - K1);
            }
            v[u] = *(const float4*)src;      // 4 loads batched in flight
        }
        #pragma unroll
        for (int u = 0; u < 4; u++) {
            float r0, r1, r2, r3;
            uint2 ph, pl;
            ph.x = pack_hi2(v[u].x, v[u].y, r0, r1);
            ph.y = pack_hi2(v[u].z, v[u].w, r2, r3);
            pl.x = pack_bf2(r0, r1);
            pl.y = pack_bf2(r2, r3);
            *(uint2*)&g_xhi[e[u]] = ph;      // default caching: planes stay
            *(uint2*)&g_xlo[e[u]] = pl;      // L2-resident for the GEMM
        }
    } else {
        // W transpose tile: 64 k-rows x 32 n-cols, both sides coalesced
        __shared__ float tile[WKT][WNT + 1];
        const int wb   = (int)blockIdx.x - XBLOCKS;
        const int k0   = (wb % (KTOT / WKT)) * WKT;   // mult of 64; never
        const int n0   = (wb / (KTOT / WKT)) * WNT;   // straddles K1=768
        const float* W = (k0 < K1) ? (W_in + (size_t)k0 * HD)
                                   : (W_h + (size_t)(k0 - K1) * HD);
        #pragma unroll
        for (int i = 0; i < 8; i++) {
            const int e2 = tid + i * 256;
            const int r  = e2 >> 5;
            const int c  = e2 & 31;
            tile[r][c] = W[(size_t)r * HD + n0 + c];
        }
        __syncthreads();
        #pragma unroll
        for (int i = 0; i < 4; i++) {
            const int p  = tid + i * 256;
            const int n  = p >> 5;
            const int kk = (p & 31) * 2;
            float r0, r1;
            const uint32_t hi = pack_hi2(tile[kk][n], tile[kk + 1][n], r0, r1);
            const uint32_t lo = pack_bf2(r0, r1);
            const size_t off = (size_t)(n0 + n) * KTOT + k0 + kk;
            *(uint32_t*)&g_whi[off] = hi;
            *(uint32_t*)&g_wlo[off] = lo;
        }
    }
}

// --------------------------------------------------------------------------
// Copy role: work-stealing passthrough. Skips BOTH the load and the store of
// the row each batch's GEMM scatters. Warp grabs 32 rows; 4 rows/group with
// up to 16 LDG.128 in flight. .cs hints keep the stream out of L2's hot set.
// --------------------------------------------------------------------------
__device__ __forceinline__ void copy_role(const float4* __restrict__ src,
                                          float4* __restrict__ dst,
                                          const int* __restrict__ veh_idx,
                                          int lane)
{
    for (;;) {
        int c;
        if (lane == 0) c = atomicAdd(&g_copy_ctr, 1);
        c = __shfl_sync(0xffffffffu, c, 0);
        if (c >= NUM_GRABS) return;

        const int r0   = c * 32;            // same n for the whole grab
        const int n    = r0 >> 6;
        const int skip = veh_idx[n] & (LV - 1);
        const int l0   = r0 & 63;

        for (int g = 0; g < 8; g++) {
            float4 v[16];
            size_t base = (size_t)(r0 + g * 4) * (HD / 4) + lane;
            #pragma unroll
            for (int rr = 0; rr < 4; rr++) {
                if (l0 + g * 4 + rr == skip) continue;   // dead row: no read
                #pragma unroll
                for (int q = 0; q < 4; q++)
                    v[rr * 4 + q] = ldcs(src + base + rr * 128 + q * 32);
            }
            #pragma unroll
            for (int rr = 0; rr < 4; rr++) {
                if (l0 + g * 4 + rr == skip) continue;   // GEMM writes this row
                #pragma unroll
                for (int q = 0; q < 4; q++)
                    stcs(dst + base + rr * 128 + q * 32, v[rr * 4 + q]);
            }
        }
    }
}

// --------------------------------------------------------------------------
// Fused kernel (R11-proven structure). bids [0,128): tensor-core GEMM tile
// via mma.sync bf16 with 3-term hi/lo split, 3-stage cp.async pipeline;
// epilogue scatters tanh(acc+bias) directly into out[n, veh_idx[n], :].
// All CTAs end in the copy pool.
// --------------------------------------------------------------------------
__global__ __launch_bounds__(256, 2)
void fused_kernel(const float* __restrict__ memory,
                  const int*   __restrict__ veh_idx,
                  const float* __restrict__ b_in,
                  const float* __restrict__ b_h,
                  float* __restrict__ out)
{
    // 3 stages x 16KB: per stage: xhi[128][16] | xlo | whi[128][16] | wlo
    __shared__ __align__(128) char raw[49152];

    const int tid  = threadIdx.x;
    const int bid  = blockIdx.x;
    const int lane = tid & 31;

    if (bid < GEMM_CTAS) {
        const int block_m = (bid >> 2) * BM;
        const int block_n = (bid & 3) * BN;
        const int w  = tid >> 5;
        const int wm = w >> 1;          // 0..3 -> rows wm*32
        const int wn = w & 1;           // 0..1 -> cols wn*64
        const uint32_t sbase = s2u(raw);

        // cp.async mapping: thread -> (row 0..127, 16B half)
        const int row  = tid >> 1;
        const int half = tid & 1;
        const uint32_t dxy = (uint32_t)(row * 32 + half * 16);
        const size_t gx = (size_t)(block_m + row) * KTOT + half * 8;
        const size_t gw = (size_t)(block_n + row) * KTOT + half * 8;

        auto issue = [&](int it, int buf) {
            const int k0 = it * BKS;
            const uint32_t sb = sbase + (uint32_t)buf * 16384;
            cp16(sb + dxy,          g_xhi + gx + k0);
            cp16(sb + 4096 + dxy,   g_xlo + gx + k0);
            cp16(sb + 8192 + dxy,   g_whi + gw + k0);
            cp16(sb + 12288 + dxy,  g_wlo + gw + k0);
            cp_commit();
        };

        // ldmatrix lane offsets
        uint32_t aoff[2];
        #pragma unroll
        for (int i = 0; i < 2; i++) {
            const int r = wm * 32 + i * 16 + (lane & 7) + ((lane >> 3) & 1) * 8;
            aoff[i] = (uint32_t)(r * 32 + ((lane >> 4) & 1) * 16);
        }
        uint32_t boff[4];
        #pragma unroll
        for (int p = 0; p < 4; p++) {
            const int r = wn * 64 + p * 16 + (lane & 7) + ((lane >> 4) & 1) * 8;
            boff[p] = (uint32_t)(r * 32 + ((lane >> 3) & 1) * 16);
        }

        float d[2][8][4];
        #pragma unroll
        for (int i = 0; i < 2; i++)
            #pragma unroll
            for (int j = 0; j < 8; j++)
                #pragma unroll
                for (int q = 0; q < 4; q++) d[i][j][q] = 0.0f;

        issue(0, 0);
        issue(1, 1);

        int buf = 0, nbuf = 2;
        for (int it = 0; it < NIT; it++) {
            if (it + 2 < NIT) cp_wait<1>(); else cp_wait<0>();
            __syncthreads();
            if (it + 2 < NIT) issue(it + 2, nbuf);

            const uint32_t sb = sbase + (uint32_t)buf * 16384;
            uint32_t ah[2][4], al[2][4], bb[8][2];
            ldsm4(ah[0], sb + aoff[0]);
            ldsm4(ah[1], sb + aoff[1]);
            ldsm4(al[0], sb + 4096 + aoff[0]);
            ldsm4(al[1], sb + 4096 + aoff[1]);
            #pragma unroll
            for (int p = 0; p < 4; p++) {
                uint32_t r[4];
                ldsm4(r, sb + 8192 + boff[p]);      // W hi
                bb[2 * p][0] = r[0]; bb[2 * p][1] = r[1];
                bb[2 * p + 1][0] = r[2]; bb[2 * p + 1][1] = r[3];
            }
            #pragma unroll
            for (int i = 0; i < 2; i++)
                #pragma unroll
                for (int j = 0; j < 8; j++) {
                    mma16816(d[i][j], ah[i], bb[j]);   // hi*hi
                    mma16816(d[i][j], al[i], bb[j]);   // lo*hi
                }
            #pragma unroll
            for (int p = 0; p < 4; p++) {
                uint32_t r[4];
                ldsm4(r, sb + 12288 + boff[p]);     // W lo
                bb[2 * p][0] = r[0]; bb[2 * p][1] = r[1];
                bb[2 * p + 1][0] = r[2]; bb[2 * p + 1][1] = r[3];
            }
            #pragma unroll
            for (int i = 0; i < 2; i++)
                #pragma unroll
                for (int j = 0; j < 8; j++)
                    mma16816(d[i][j], ah[i], bb[j]);   // hi*lo

            buf  = (buf  == 2) ? 0 : buf + 1;
            nbuf = (nbuf == 2) ? 0 : nbuf + 1;
        }

        // epilogue: bias + tanh -> scatter directly to out[n, idx[n], :]
        float2 bias[8];
        #pragma unroll
        for (int j = 0; j < 8; j++) {
            const int col = block_n + wn * 64 + j * 8 + (lane & 3) * 2;
            bias[j].x = b_in[col] + b_h[col];
            bias[j].y = b_in[col + 1] + b_h[col + 1];
        }
        #pragma unroll
        for (int i = 0; i < 2; i++) {
            const int m0 = block_m + wm * 32 + i * 16 + (lane >> 2);
            const int m1 = m0 + 8;
            const size_t base0 = ((size_t)m0 * LV + (veh_idx[m0] & (LV - 1))) * HD;
            const size_t base1 = ((size_t)m1 * LV + (veh_idx[m1] & (LV - 1))) * HD;
            #pragma unroll
            for (int j = 0; j < 8; j++) {
                const int col = block_n + wn * 64 + j * 8 + (lane & 3) * 2;
                float2 v0, v1;
                v0.x = tanhf(d[i][j][0] + bias[j].x);
                v0.y = tanhf(d[i][j][1] + bias[j].y);
                v1.x = tanhf(d[i][j][2] + bias[j].x);
                v1.y = tanhf(d[i][j][3] + bias[j].y);
                *(float2*)&out[base0 + col] = v0;
                *(float2*)&out[base1 + col] = v1;
            }
        }
    }

    // Copy pool (copy-only CTAs arrive here immediately; no smem used).
    copy_role((const float4*)memory, (float4*)out, veh_idx, lane);
}

extern "C" void kernel_launch(void* const* d_in, const int* in_sizes, int n_in,
                              void* d_out, int out_size)
{
    const float* memory    = (const float*)d_in[0];
    const int*   veh_idx   = (const int*)d_in[1];
    const float* veh_repr  = (const float*)d_in[2];
    const float* cust_repr = (const float*)d_in[3];
    const float* edge_emb  = (const float*)d_in[4];
    const float* W_in      = (const float*)d_in[5];
    const float* b_in      = (const float*)d_in[6];
    const float* W_h       = (const float*)d_in[7];
    const float* b_h       = (const float*)d_in[8];
    float*       out       = (float*)d_out;

    prep_kernel<<<XBLOCKS + WBLOCKS, 256>>>(memory, veh_idx, veh_repr,
                                            cust_repr, edge_emb, W_in, W_h);
    fused_kernel<<<TOTAL_CTAS, 256>>>(memory, veh_idx, b_in, b_h, out);
}